// round 10
// baseline (speedup 1.0000x reference)
#include <cuda_runtime.h>
#include <math.h>

// Problem constants
#define BB 2
#define SS 8192
#define CC 64
#define MMG 32
#define GG (SS / MMG)          // 256 groups per batch
#define BCS (BB * CC * SS)
#define WST 64                 // weight row stride ([k][c] layout; broadcast loads)

// Scratch (device globals — allocation-free)
__device__ float g_Pf[BCS];
__device__ float g_Qf[BCS];
__device__ float g_Pe[BCS];
__device__ float g_Qe[BCS];
__device__ float g_Ef[BCS];
__device__ float g_Eg[BCS];
__device__ float g_F1[BCS];
__device__ float g_agg[BCS];

typedef unsigned long long u64;

// per-team named barrier: 256 threads of team t sync on barrier id t+1
#define TEAM_BAR(t) asm volatile("bar.sync %0, 256;" :: "r"((t) + 1) : "memory")

// ---------------------------------------------------------------------------
// packed fp32 helpers (Blackwell f32x2)
// ---------------------------------------------------------------------------
__device__ __forceinline__ void ffma2(u64& d, u64 a, u64 b) {
    asm("fma.rn.f32x2 %0, %1, %2, %0;" : "+l"(d) : "l"(a), "l"(b));
}
__device__ __forceinline__ u64 splat2(float a) {
    u64 r; asm("mov.b64 %0, {%1, %1};" : "=l"(r) : "f"(a)); return r;
}
__device__ __forceinline__ u64 pack2(float x, float y) {
    u64 r; asm("mov.b64 %0, {%1, %2};" : "=l"(r) : "f"(x), "f"(y)); return r;
}
__device__ __forceinline__ float2 unpack2(u64 v) {
    float2 r; asm("mov.b64 {%0, %1}, %2;" : "=f"(r.x), "=f"(r.y) : "l"(v)); return r;
}

// Packed matmul, scalar acts (splat in-loop): acc{0,1}[i] += Wt[k][cb+2i..] * A{0,1}[k][lane]
__device__ __forceinline__ void mmT2(u64 acc0[4], u64 acc1[4],
                                     const float* __restrict__ sWt, int cb,
                                     const float* __restrict__ sA0,
                                     const float* __restrict__ sA1, int lane) {
#pragma unroll 8
    for (int k = 0; k < 64; k++) {
        ulonglong2 wlo = *reinterpret_cast<const ulonglong2*>(sWt + k * WST + cb);
        ulonglong2 whi = *reinterpret_cast<const ulonglong2*>(sWt + k * WST + cb + 4);
        u64 a0 = splat2(sA0[k * 32 + lane]);
        u64 a1 = splat2(sA1[k * 32 + lane]);
        ffma2(acc0[0], wlo.x, a0); ffma2(acc0[1], wlo.y, a0);
        ffma2(acc0[2], whi.x, a0); ffma2(acc0[3], whi.y, a0);
        ffma2(acc1[0], wlo.x, a1); ffma2(acc1[1], wlo.y, a1);
        ffma2(acc1[2], whi.x, a1); ffma2(acc1[3], whi.y, a1);
    }
}

// Packed matmul, dup-packed acts (direct LDS.64, no splat)
__device__ __forceinline__ void mmT2d(u64 acc0[4], u64 acc1[4],
                                      const float* __restrict__ sWt, int cb,
                                      const u64* __restrict__ A0,
                                      const u64* __restrict__ A1, int lane) {
#pragma unroll 8
    for (int k = 0; k < 64; k++) {
        ulonglong2 wlo = *reinterpret_cast<const ulonglong2*>(sWt + k * WST + cb);
        ulonglong2 whi = *reinterpret_cast<const ulonglong2*>(sWt + k * WST + cb + 4);
        u64 a0 = A0[k * 32 + lane];
        u64 a1 = A1[k * 32 + lane];
        ffma2(acc0[0], wlo.x, a0); ffma2(acc0[1], wlo.y, a0);
        ffma2(acc0[2], whi.x, a0); ffma2(acc0[3], whi.y, a0);
        ffma2(acc1[0], wlo.x, a1); ffma2(acc1[1], wlo.y, a1);
        ffma2(acc1[2], whi.x, a1); ffma2(acc1[3], whi.y, a1);
    }
}

// scalar helper used by kernel A
__device__ __forceinline__ void mm64_acc(float acc[8], const float* __restrict__ sW,
                                         int wstride, int cbase,
                                         const float* __restrict__ sA, int lane) {
#pragma unroll 4
    for (int q = 0; q < 16; q++) {
        float a0 = sA[(4 * q + 0) * 32 + lane];
        float a1 = sA[(4 * q + 1) * 32 + lane];
        float a2 = sA[(4 * q + 2) * 32 + lane];
        float a3 = sA[(4 * q + 3) * 32 + lane];
#pragma unroll
        for (int i = 0; i < 8; i++) {
            float4 w = *reinterpret_cast<const float4*>(&sW[(cbase + i) * wstride + 4 * q]);
            acc[i] = fmaf(w.x, a0, acc[i]);
            acc[i] = fmaf(w.y, a1, acc[i]);
            acc[i] = fmaf(w.z, a2, acc[i]);
            acc[i] = fmaf(w.w, a3, acc[i]);
        }
    }
}

// ---------------------------------------------------------------------------
// Kernel A: per-point linear projections — unchanged
// ---------------------------------------------------------------------------
struct SmemA {
    float Wpf[64 * 64];
    float Wqf[64 * 64];
    float Wf1[64 * 64];
    float W1x[64 * 8];
    float Wex[64 * 8];
    float W2x[64 * 8];
    float F1t[64 * 32];
    float F2t[64 * 32];
    float X1[3 * 32];
    float X2[3 * 32];
};

__global__ void kernelA(const float* __restrict__ xyz1, const float* __restrict__ feat1,
                        const float* __restrict__ xyz2, const float* __restrict__ feat2,
                        const float* __restrict__ w10, const float* __restrict__ b10,
                        const float* __restrict__ wx1, const float* __restrict__ bx1,
                        const float* __restrict__ wx2, const float* __restrict__ bx2,
                        const float* __restrict__ w30, const float* __restrict__ b30) {
    extern __shared__ float smem_raw[];
    SmemA& s = *reinterpret_cast<SmemA*>(smem_raw);
    int tid = threadIdx.x;
    int t = blockIdx.x;
    int b = t >> 8;
    int s0 = (t & 255) * 32;

    for (int idx = tid; idx < 4096; idx += 256) {
        int c = idx >> 6, j = idx & 63;
        s.Wpf[idx] = w10[c * 138 + 10 + j];
        s.Wqf[idx] = w10[c * 138 + 74 + j];
        s.Wf1[idx] = w30[c * 192 + 64 + j];
    }
    for (int idx = tid; idx < 384; idx += 256) {
        int c = idx / 6, j = idx % 6;
        s.W1x[c * 8 + j] = w10[c * 138 + j];
        s.Wex[c * 8 + j] = wx1[c * 10 + j];
        s.W2x[c * 8 + j] = wx2[c * 10 + j];
    }
    for (int idx = tid; idx < 2048; idx += 256) {
        int c = idx >> 5, k = idx & 31;
        s.F1t[idx] = feat1[b * CC * SS + c * SS + s0 + k];
        s.F2t[idx] = feat2[b * CC * SS + c * SS + s0 + k];
    }
    for (int idx = tid; idx < 96; idx += 256) {
        int i = idx >> 5, k = idx & 31;
        s.X1[idx] = xyz1[b * 3 * SS + i * SS + s0 + k];
        s.X2[idx] = xyz2[b * 3 * SS + i * SS + s0 + k];
    }
    __syncthreads();

    int lane = tid & 31;
    int cb = (tid >> 5) * 8;
    float x10 = s.X1[lane], x11 = s.X1[32 + lane], x12 = s.X1[64 + lane];
    float x20 = s.X2[lane], x21 = s.X2[32 + lane], x22 = s.X2[64 + lane];

    float accPf[8], accQf[8], accF1[8];
#pragma unroll
    for (int i = 0; i < 8; i++) {
        accPf[i] = __ldg(&b10[cb + i]);
        accQf[i] = 0.f;
        accF1[i] = __ldg(&b30[cb + i]);
    }
    mm64_acc(accPf, s.Wpf, 64, cb, s.F1t, lane);
    mm64_acc(accF1, s.Wf1, 64, cb, s.F1t, lane);
    mm64_acc(accQf, s.Wqf, 64, cb, s.F2t, lane);

#pragma unroll
    for (int i = 0; i < 8; i++) {
        int c = cb + i;
        long base = (long)b * CC * SS + (long)c * SS + s0 + lane;
        float pf = accPf[i] + s.W1x[c * 8 + 0] * x10 + s.W1x[c * 8 + 1] * x11 + s.W1x[c * 8 + 2] * x12;
        float qf = accQf[i] + s.W1x[c * 8 + 3] * x20 + s.W1x[c * 8 + 4] * x21 + s.W1x[c * 8 + 5] * x22;
        g_Pf[base] = pf;
        g_Qf[base] = qf;
        g_F1[base] = accF1[i];
        g_Pe[base] = __ldg(&bx1[c]) + s.Wex[c * 8 + 0] * x10 + s.Wex[c * 8 + 1] * x11 + s.Wex[c * 8 + 2] * x12;
        g_Qe[base] = s.Wex[c * 8 + 3] * x20 + s.Wex[c * 8 + 4] * x21 + s.Wex[c * 8 + 5] * x22;
        g_Ef[base] = __ldg(&bx2[c]) + s.W2x[c * 8 + 0] * x10 + s.W2x[c * 8 + 1] * x11 + s.W2x[c * 8 + 2] * x12;
        g_Eg[base] = s.W2x[c * 8 + 3] * x10 + s.W2x[c * 8 + 4] * x11 + s.W2x[c * 8 + 5] * x12;
    }
}

// ---------------------------------------------------------------------------
// Kernel B: stage 1 — 2 teams, dup-packed H/U acts, transposed softmax epilogue
// grid = BB*GG*2; 512 threads
// ---------------------------------------------------------------------------
struct SmemB {
    float W11t[64 * WST];
    float W20t[128 * WST];
    float W21t[64 * WST];
    float W1d[64 * 4];
    float Wed[64 * 4];
    float B11[64], B20[64], B21[64];
    float Pf[64 * 16], Pe[64 * 16];
    float X1h[3 * 16];
    float X2[3 * 32];
    float PEa[2][64 * 32], PEb[2][64 * 32];   // scalar acts; dead space doubles as epi scratch
    float PNa[2][64 * 32], PNb[2][64 * 32];
    u64 Had[2][64 * 32], Hbd[2][64 * 32];     // dup-packed H/U acts
};

__global__ void __launch_bounds__(512, 1)
kernelB(const float* __restrict__ xyz1, const float* __restrict__ xyz2,
        const float* __restrict__ w10, const float* __restrict__ wx1,
        const float* __restrict__ w11, const float* __restrict__ b11,
        const float* __restrict__ w20, const float* __restrict__ b20,
        const float* __restrict__ w21, const float* __restrict__ b21) {
    extern __shared__ float smem_raw[];
    SmemB& s = *reinterpret_cast<SmemB*>(smem_raw);
    int tid = threadIdx.x;
    int bid = blockIdx.x;
    int b = bid >> 9;
    int g = (bid >> 1) & 255;
    int half = bid & 1;
    int sb = g * MMG;
    int sbh = sb + half * 16;
    long cbase = (long)b * CC * SS;

    for (int idx = tid; idx < 4096; idx += 512) {
        int c = idx >> 6, k = idx & 63;
        s.W11t[k * WST + c] = w11[idx];
        s.W21t[k * WST + c] = w21[idx];
    }
    for (int idx = tid; idx < 8192; idx += 512) {
        int c = idx >> 7, k = idx & 127;
        s.W20t[k * WST + c] = w20[idx];
    }
    if (tid < 256) {
        int c = tid >> 2, j = tid & 3;
        s.W1d[tid] = w10[c * 138 + 6 + j];
        s.Wed[tid] = wx1[c * 10 + 6 + j];
    }
    if (tid < 64) {
        s.B11[tid] = b11[tid];
        s.B20[tid] = b20[tid];
        s.B21[tid] = b21[tid];
    }
    for (int idx = tid; idx < 1024; idx += 512) {
        int c = idx >> 4, sl = idx & 15;
        s.Pf[c * 16 + sl] = g_Pf[cbase + (long)c * SS + sbh + sl];
        s.Pe[c * 16 + sl] = g_Pe[cbase + (long)c * SS + sbh + sl];
    }
    if (tid >= 448 && tid < 496) {
        int i = tid - 448;
        int d = i >> 4, sl = i & 15;
        s.X1h[d * 16 + sl] = xyz1[b * 3 * SS + d * SS + sbh + sl];
    }
    if (tid >= 320 && tid < 416) {
        int i = tid - 320;
        int d = i >> 5, j = i & 31;
        s.X2[d * 32 + j] = xyz2[b * 3 * SS + d * SS + sb + j];
    }
    __syncthreads();

    int lane = tid & 31;
    int wid = tid >> 5;
    int team = wid >> 3;
    int w8 = wid & 7;
    int cb = w8 * 8;
    long outbase = cbase + sb;

    float qf[8], qe[8];
#pragma unroll
    for (int i = 0; i < 8; i++) {
        long base = cbase + (long)(cb + i) * SS + sb + lane;
        qf[i] = __ldg(&g_Qf[base]);
        qe[i] = __ldg(&g_Qe[base]);
    }

    float nx0 = s.X2[lane], nx1 = s.X2[32 + lane], nx2 = s.X2[64 + lane];

    u64* Ha = s.Had[team];   u64* Hb = s.Hbd[team];
    float* PEa = s.PEa[team]; float* PEb = s.PEb[team];
    float* PNa = s.PNa[team]; float* PNb = s.PNb[team];
    // warp-private epilogue scratch: 512 floats carved from dead PE buffers
    float* esc = (w8 < 4) ? &s.PEa[team][w8 * 512] : &s.PEb[team][(w8 - 4) * 512];

    for (int p = 0; p < 4; p++) {
        int slL0 = 4 * p + 2 * team;
        int slL1 = slL0 + 1;
        int sl0 = half * 16 + slL0;
        int sl1 = sl0 + 1;

        // --- step 1: dynamic parts for both s ---
        {
            float pa0 = s.X1h[slL0], pa1 = s.X1h[16 + slL0], pa2 = s.X1h[32 + slL0];
            float pb0 = s.X1h[slL1], pb1 = s.X1h[16 + slL1], pb2 = s.X1h[32 + slL1];
            float da0 = nx0 - pa0, da1 = nx1 - pa1, da2 = nx2 - pa2;
            float db0 = nx0 - pb0, db1 = nx1 - pb1, db2 = nx2 - pb2;
            float ea = sqrtf(da0 * da0 + da1 * da1 + da2 * da2 + 1e-20f);
            float eb = sqrtf(db0 * db0 + db1 * db1 + db2 * db2 + 1e-20f);
#pragma unroll
            for (int i = 0; i < 8; i++) {
                int c = cb + i;
                float w0 = s.W1d[c * 4 + 0], w1 = s.W1d[c * 4 + 1], w2 = s.W1d[c * 4 + 2], w3 = s.W1d[c * 4 + 3];
                float ha = s.Pf[c * 16 + slL0] + qf[i] + w0 * da0 + w1 * da1 + w2 * da2 + w3 * ea;
                float hb = s.Pf[c * 16 + slL1] + qf[i] + w0 * db0 + w1 * db1 + w2 * db2 + w3 * eb;
                Ha[c * 32 + lane] = splat2(fmaxf(ha, 0.f));
                Hb[c * 32 + lane] = splat2(fmaxf(hb, 0.f));
                float v0 = s.Wed[c * 4 + 0], v1 = s.Wed[c * 4 + 1], v2 = s.Wed[c * 4 + 2], v3 = s.Wed[c * 4 + 3];
                float pea = s.Pe[c * 16 + slL0] + qe[i] + v0 * da0 + v1 * da1 + v2 * da2 + v3 * ea;
                float peb = s.Pe[c * 16 + slL1] + qe[i] + v0 * db0 + v1 * db1 + v2 * db2 + v3 * eb;
                PEa[c * 32 + lane] = fmaxf(pea, 0.f);
                PEb[c * 32 + lane] = fmaxf(peb, 0.f);
            }
        }
        TEAM_BAR(team);

        // --- step 2: pi_new = relu(W1_1 @ H + b1_1) ---
        u64 acc0[4], acc1[4];
#pragma unroll
        for (int i = 0; i < 4; i++) {
            u64 bv = *reinterpret_cast<const u64*>(&s.B11[cb + 2 * i]);
            acc0[i] = bv; acc1[i] = bv;
        }
        mmT2d(acc0, acc1, s.W11t, cb, Ha, Hb, lane);
#pragma unroll
        for (int i = 0; i < 4; i++) {
            float2 ra = unpack2(acc0[i]), rb = unpack2(acc1[i]);
            PNa[(cb + 2 * i) * 32 + lane] = fmaxf(ra.x, 0.f);
            PNa[(cb + 2 * i + 1) * 32 + lane] = fmaxf(ra.y, 0.f);
            PNb[(cb + 2 * i) * 32 + lane] = fmaxf(rb.x, 0.f);
            PNb[(cb + 2 * i + 1) * 32 + lane] = fmaxf(rb.y, 0.f);
        }
        TEAM_BAR(team);

        // --- step 3: U = relu(W2_0 @ [PE; PN] + b2_0) -> dup-store into H ---
#pragma unroll
        for (int i = 0; i < 4; i++) {
            u64 bv = *reinterpret_cast<const u64*>(&s.B20[cb + 2 * i]);
            acc0[i] = bv; acc1[i] = bv;
        }
        mmT2(acc0, acc1, s.W20t, cb, PEa, PEb, lane);
        mmT2(acc0, acc1, s.W20t + 64 * WST, cb, PNa, PNb, lane);
#pragma unroll
        for (int i = 0; i < 4; i++) {
            float2 ra = unpack2(acc0[i]), rb = unpack2(acc1[i]);
            Ha[(cb + 2 * i) * 32 + lane] = splat2(fmaxf(ra.x, 0.f));
            Ha[(cb + 2 * i + 1) * 32 + lane] = splat2(fmaxf(ra.y, 0.f));
            Hb[(cb + 2 * i) * 32 + lane] = splat2(fmaxf(rb.x, 0.f));
            Hb[(cb + 2 * i + 1) * 32 + lane] = splat2(fmaxf(rb.y, 0.f));
        }
        TEAM_BAR(team);

        // --- step 4: logits = relu(W2_1 @ U + b2_1) ---
#pragma unroll
        for (int i = 0; i < 4; i++) {
            u64 bv = *reinterpret_cast<const u64*>(&s.B21[cb + 2 * i]);
            acc0[i] = bv; acc1[i] = bv;
        }
        mmT2d(acc0, acc1, s.W21t, cb, Ha, Hb, lane);

        // --- transposed softmax epilogue ---
        // store e into warp-private scratch: row = (2i+ch)*2 + sbit, col = lane
#pragma unroll
        for (int i = 0; i < 4; i++) {
            float2 la = unpack2(acc0[i]), lb = unpack2(acc1[i]);
            esc[((2 * i + 0) * 2 + 0) * 32 + lane] = __expf(fmaxf(la.x, 0.f));
            esc[((2 * i + 1) * 2 + 0) * 32 + lane] = __expf(fmaxf(la.y, 0.f));
            esc[((2 * i + 0) * 2 + 1) * 32 + lane] = __expf(fmaxf(lb.x, 0.f));
            esc[((2 * i + 1) * 2 + 1) * 32 + lane] = __expf(fmaxf(lb.y, 0.f));
        }
        __syncwarp();
        // lane owns (row = lane>>1, type = lane&1); row = chp*2 + sbit, chp in 0..7
        {
            int row = lane >> 1, typ = lane & 1;
            int chp = row >> 1, sbit = row & 1;
            int c = cb + chp;
            const float* pnrow = (sbit ? PNb : PNa) + c * 32;
            const float* erow = esc + row * 32;
            float sum = 0.f;
#pragma unroll 8
            for (int j = 0; j < 32; j++) {
                int jj = (j + lane) & 31;
                float v = erow[jj];
                float m = typ ? pnrow[jj] : 1.0f;
                sum = fmaf(v, m, sum);
            }
            float partner = __shfl_xor_sync(0xffffffffu, sum, 1);
            if (typ == 1) {
                int sg = sbit ? sl1 : sl0;
                g_agg[outbase + (long)c * SS + sg] = __fdividef(sum, partner);
            }
        }
        TEAM_BAR(team);
    }
}

// ---------------------------------------------------------------------------
// Kernel C: stage 2 — 2 teams, all-dup acts, transposed masked-softmax epilogue
// grid = BB*GG*2; 512 threads; hoisted G = W30b @ pi_agg
// ---------------------------------------------------------------------------
struct SmemC {
    float W30at[64 * WST];
    float W30bt[64 * WST];
    float W31t[64 * WST];
    float W2d[64 * 4];
    float B31[64];
    float Eg[64 * 32];
    float Ef_h[64 * 16], F1_h[64 * 16];
    float X1[3 * 32];
    float G[64 * 32];
    u64 PAGd[64 * 32];                       // dup-packed pi_agg
    u64 Pad[2][64 * 32], Pbd[2][64 * 32];    // dup acts; dead space doubles as epi scratch
    u64 Tad[2][64 * 32], Tbd[2][64 * 32];
};

__global__ void __launch_bounds__(512, 1)
kernelC(const float* __restrict__ xyz1, const float* __restrict__ wx2,
        const float* __restrict__ w30, const float* __restrict__ w31,
        const float* __restrict__ b31, float* __restrict__ out) {
    extern __shared__ float smem_raw[];
    SmemC& s = *reinterpret_cast<SmemC*>(smem_raw);
    int tid = threadIdx.x;
    int bid = blockIdx.x;
    int b = bid >> 9;
    int g = (bid >> 1) & 255;
    int half = bid & 1;
    int sb = g * MMG;
    int sbh = sb + half * 16;
    long cbase = (long)b * CC * SS;

    for (int idx = tid; idx < 4096; idx += 512) {
        int c = idx >> 6, k = idx & 63;
        s.W30at[k * WST + c] = w30[c * 192 + k];
        s.W30bt[k * WST + c] = w30[c * 192 + 128 + k];
        s.W31t[k * WST + c] = w31[c * 64 + k];
    }
    if (tid < 256) {
        int c = tid >> 2, j = tid & 3;
        s.W2d[tid] = wx2[c * 10 + 6 + j];
    }
    if (tid < 64) s.B31[tid] = b31[tid];
    for (int idx = tid; idx < 2048; idx += 512) {
        int c = idx >> 5, k = idx & 31;
        long base = cbase + (long)c * SS + sb + k;
        s.Eg[idx] = g_Eg[base];
        s.PAGd[idx] = splat2(g_agg[base]);
    }
    for (int idx = tid; idx < 1024; idx += 512) {
        int c = idx >> 4, sl = idx & 15;
        s.Ef_h[c * 16 + sl] = g_Ef[cbase + (long)c * SS + sbh + sl];
        s.F1_h[c * 16 + sl] = g_F1[cbase + (long)c * SS + sbh + sl];
    }
    if (tid >= 384 && tid < 480) {
        int i = tid - 384;
        int d = i >> 5, k = i & 31;
        s.X1[d * 32 + k] = xyz1[b * 3 * SS + d * SS + sb + k];
    }
    __syncthreads();

    int lane = tid & 31;
    int wid = tid >> 5;
    int team = wid >> 3;
    int w8 = wid & 7;
    int cb = w8 * 8;
    long outbase = cbase + sb;

    // --- G = W30b @ pi_agg (s-independent): 16 warps x 4 channels ---
    {
        int c4 = wid * 4;
        u64 gacc[2] = {0ull, 0ull};
#pragma unroll 8
        for (int k = 0; k < 64; k++) {
            ulonglong2 w = *reinterpret_cast<const ulonglong2*>(s.W30bt + k * WST + c4);
            u64 a = s.PAGd[k * 32 + lane];
            ffma2(gacc[0], w.x, a);
            ffma2(gacc[1], w.y, a);
        }
        float2 v0 = unpack2(gacc[0]), v1 = unpack2(gacc[1]);
        s.G[(c4 + 0) * 32 + lane] = v0.x;
        s.G[(c4 + 1) * 32 + lane] = v0.y;
        s.G[(c4 + 2) * 32 + lane] = v1.x;
        s.G[(c4 + 3) * 32 + lane] = v1.y;
    }
    __syncthreads();

    float nx0 = s.X1[lane], nx1 = s.X1[32 + lane], nx2 = s.X1[64 + lane];

    u64* Pa = s.Pad[team]; u64* Pb = s.Pbd[team];
    u64* Ta = s.Tad[team]; u64* Tb = s.Tbd[team];
    // warp-private epilogue scratch: 512 floats carved from dead Pa region
    float* esc = reinterpret_cast<float*>(s.Pad[team]) + w8 * 512;
    const float* pagf = reinterpret_cast<const float*>(s.PAGd);

    for (int p = 0; p < 4; p++) {
        int slL0 = 4 * p + 2 * team;
        int slL1 = slL0 + 1;
        int sl0 = half * 16 + slL0;
        int sl1 = sl0 + 1;

        // --- step 1: pc_enc for both s ---
        {
            float pa0 = s.X1[sl0], pa1 = s.X1[32 + sl0], pa2 = s.X1[64 + sl0];
            float pb0 = s.X1[sl1], pb1 = s.X1[32 + sl1], pb2 = s.X1[64 + sl1];
            float da0 = nx0 - pa0, da1 = nx1 - pa1, da2 = nx2 - pa2;
            float db0 = nx0 - pb0, db1 = nx1 - pb1, db2 = nx2 - pb2;
            float ea = sqrtf(da0 * da0 + da1 * da1 + da2 * da2 + 1e-20f);
            float eb = sqrtf(db0 * db0 + db1 * db1 + db2 * db2 + 1e-20f);
#pragma unroll
            for (int i = 0; i < 8; i++) {
                int c = cb + i;
                float w0 = s.W2d[c * 4 + 0], w1 = s.W2d[c * 4 + 1], w2 = s.W2d[c * 4 + 2], w3 = s.W2d[c * 4 + 3];
                float base_c = s.Eg[c * 32 + lane];
                float va = s.Ef_h[c * 16 + slL0] + base_c + w0 * da0 + w1 * da1 + w2 * da2 + w3 * ea;
                float vb = s.Ef_h[c * 16 + slL1] + base_c + w0 * db0 + w1 * db1 + w2 * db2 + w3 * eb;
                Pa[c * 32 + lane] = splat2(fmaxf(va, 0.f));
                Pb[c * 32 + lane] = splat2(fmaxf(vb, 0.f));
            }
        }
        TEAM_BAR(team);

        // --- step 2: T = relu(G + F1[.,sl] + W3_0a @ pc_enc) ---
        u64 acc0[4], acc1[4];
#pragma unroll
        for (int i = 0; i < 4; i++) {
            int c0 = cb + 2 * i, c1 = c0 + 1;
            float g0 = s.G[c0 * 32 + lane], g1 = s.G[c1 * 32 + lane];
            acc0[i] = pack2(g0 + s.F1_h[c0 * 16 + slL0], g1 + s.F1_h[c1 * 16 + slL0]);
            acc1[i] = pack2(g0 + s.F1_h[c0 * 16 + slL1], g1 + s.F1_h[c1 * 16 + slL1]);
        }
        mmT2d(acc0, acc1, s.W30at, cb, Pa, Pb, lane);
#pragma unroll
        for (int i = 0; i < 4; i++) {
            float2 ra = unpack2(acc0[i]), rb = unpack2(acc1[i]);
            Ta[(cb + 2 * i) * 32 + lane] = splat2(fmaxf(ra.x, 0.f));
            Ta[(cb + 2 * i + 1) * 32 + lane] = splat2(fmaxf(ra.y, 0.f));
            Tb[(cb + 2 * i) * 32 + lane] = splat2(fmaxf(rb.x, 0.f));
            Tb[(cb + 2 * i + 1) * 32 + lane] = splat2(fmaxf(rb.y, 0.f));
        }
        TEAM_BAR(team);

        // --- step 3: logits = relu(W3_1 @ T + b3_1) ---
#pragma unroll
        for (int i = 0; i < 4; i++) {
            u64 bv = *reinterpret_cast<const u64*>(&s.B31[cb + 2 * i]);
            acc0[i] = bv; acc1[i] = bv;
        }
        mmT2d(acc0, acc1, s.W31t, cb, Ta, Tb, lane);

        // --- transposed masked-softmax epilogue ---
#pragma unroll
        for (int i = 0; i < 4; i++) {
            float2 la = unpack2(acc0[i]), lb = unpack2(acc1[i]);
            float e00 = (lane == sl0) ? 0.f : __expf(fmaxf(la.x, 0.f));
            float e01 = (lane == sl0) ? 0.f : __expf(fmaxf(la.y, 0.f));
            float e10 = (lane == sl1) ? 0.f : __expf(fmaxf(lb.x, 0.f));
            float e11 = (lane == sl1) ? 0.f : __expf(fmaxf(lb.y, 0.f));
            esc[((2 * i + 0) * 2 + 0) * 32 + lane] = e00;
            esc[((2 * i + 1) * 2 + 0) * 32 + lane] = e01;
            esc[((2 * i + 0) * 2 + 1) * 32 + lane] = e10;
            esc[((2 * i + 1) * 2 + 1) * 32 + lane] = e11;
        }
        __syncwarp();
        {
            int row = lane >> 1, typ = lane & 1;
            int chp = row >> 1, sbit = row & 1;
            int c = cb + chp;
            const float* erow = esc + row * 32;
            float sum = 0.f;
#pragma unroll 8
            for (int j = 0; j < 32; j++) {
                int jj = (j + lane) & 31;
                float v = erow[jj];
                float m = typ ? pagf[(c * 32 + jj) * 2] : 1.0f;
                sum = fmaf(v, m, sum);
            }
            float partner = __shfl_xor_sync(0xffffffffu, sum, 1);
            if (typ == 1) {
                int sg = sbit ? sl1 : sl0;
                out[outbase + (long)c * SS + sg] = __fdividef(sum, partner);
            }
        }
        TEAM_BAR(team);
    }
}

// ---------------------------------------------------------------------------
extern "C" void kernel_launch(void* const* d_in, const int* in_sizes, int n_in,
                              void* d_out, int out_size) {
    const float* xyz1 = (const float*)d_in[0];
    const float* feat1 = (const float*)d_in[1];
    const float* xyz2 = (const float*)d_in[2];
    const float* feat2 = (const float*)d_in[3];
    const float* w10 = (const float*)d_in[4];
    const float* b10 = (const float*)d_in[5];
    const float* w11 = (const float*)d_in[6];
    const float* b11 = (const float*)d_in[7];
    const float* wx1 = (const float*)d_in[8];
    const float* bx1 = (const float*)d_in[9];
    const float* wx2 = (const float*)d_in[10];
    const float* bx2 = (const float*)d_in[11];
    const float* w20 = (const float*)d_in[12];
    const float* b20 = (const float*)d_in[13];
    const float* w21 = (const float*)d_in[14];
    const float* b21 = (const float*)d_in[15];
    const float* w30 = (const float*)d_in[16];
    const float* b30 = (const float*)d_in[17];
    const float* w31 = (const float*)d_in[18];
    const float* b31 = (const float*)d_in[19];
    float* out = (float*)d_out;

    cudaFuncSetAttribute(kernelA, cudaFuncAttributeMaxDynamicSharedMemorySize, (int)sizeof(SmemA));
    cudaFuncSetAttribute(kernelB, cudaFuncAttributeMaxDynamicSharedMemorySize, (int)sizeof(SmemB));
    cudaFuncSetAttribute(kernelC, cudaFuncAttributeMaxDynamicSharedMemorySize, (int)sizeof(SmemC));

    kernelA<<<(BB * SS) / 32, 256, sizeof(SmemA)>>>(xyz1, feat1, xyz2, feat2,
                                                    w10, b10, wx1, bx1, wx2, bx2, w30, b30);
    kernelB<<<BB * GG * 2, 512, sizeof(SmemB)>>>(xyz1, xyz2, w10, wx1,
                                                 w11, b11, w20, b20, w21, b21);
    kernelC<<<BB * GG * 2, 512, sizeof(SmemC)>>>(xyz1, wx2, w30, w31, b31, out);
}

// round 12
// speedup vs baseline: 1.1051x; 1.1051x over previous
#include <cuda_runtime.h>
#include <math.h>

// Problem constants
#define BB 2
#define SS 8192
#define CC 64
#define MMG 32
#define GG (SS / MMG)          // 256 groups per batch
#define BCS (BB * CC * SS)
#define WST 64                 // weight row stride ([k][c] layout; broadcast loads)

// Scratch (device globals — allocation-free)
__device__ float g_Pf[BCS];
__device__ float g_Qf[BCS];
__device__ float g_Pe[BCS];
__device__ float g_Qe[BCS];
__device__ float g_Ef[BCS];
__device__ float g_Eg[BCS];
__device__ float g_F1[BCS];
__device__ float g_agg[BCS];

typedef unsigned long long u64;

// per-team named barrier: 256 threads of team t sync on barrier id t+1
#define TEAM_BAR(t) asm volatile("bar.sync %0, 256;" :: "r"((t) + 1) : "memory")

// ---------------------------------------------------------------------------
// packed fp32 helpers (Blackwell f32x2) + warp reduction
// ---------------------------------------------------------------------------
__device__ __forceinline__ void ffma2(u64& d, u64 a, u64 b) {
    asm("fma.rn.f32x2 %0, %1, %2, %0;" : "+l"(d) : "l"(a), "l"(b));
}
__device__ __forceinline__ u64 splat2(float a) {
    u64 r; asm("mov.b64 %0, {%1, %1};" : "=l"(r) : "f"(a)); return r;
}
__device__ __forceinline__ u64 pack2(float x, float y) {
    u64 r; asm("mov.b64 %0, {%1, %2};" : "=l"(r) : "f"(x), "f"(y)); return r;
}
__device__ __forceinline__ float2 unpack2(u64 v) {
    float2 r; asm("mov.b64 {%0, %1}, %2;" : "=f"(r.x), "=f"(r.y) : "l"(v)); return r;
}
// two interleaved butterfly sums (sm_100 has no redux.f32)
__device__ __forceinline__ float2 warp_rsum2(float a, float b) {
#pragma unroll
    for (int o = 16; o > 0; o >>= 1) {
        a += __shfl_xor_sync(0xffffffffu, a, o);
        b += __shfl_xor_sync(0xffffffffu, b, o);
    }
    return make_float2(a, b);
}

// Packed matmul over K=64: acc{0,1}[i] += Wt[k][cb+2i..] * A{0,1}[k][lane]
__device__ __forceinline__ void mmT2(u64 acc0[4], u64 acc1[4],
                                     const float* __restrict__ sWt, int cb,
                                     const float* __restrict__ sA0,
                                     const float* __restrict__ sA1, int lane) {
#pragma unroll 8
    for (int k = 0; k < 64; k++) {
        ulonglong2 wlo = *reinterpret_cast<const ulonglong2*>(sWt + k * WST + cb);
        ulonglong2 whi = *reinterpret_cast<const ulonglong2*>(sWt + k * WST + cb + 4);
        u64 a0 = splat2(sA0[k * 32 + lane]);
        u64 a1 = splat2(sA1[k * 32 + lane]);
        ffma2(acc0[0], wlo.x, a0); ffma2(acc0[1], wlo.y, a0);
        ffma2(acc0[2], whi.x, a0); ffma2(acc0[3], whi.y, a0);
        ffma2(acc1[0], wlo.x, a1); ffma2(acc1[1], wlo.y, a1);
        ffma2(acc1[2], whi.x, a1); ffma2(acc1[3], whi.y, a1);
    }
}

// scalar helper used by kernel A
__device__ __forceinline__ void mm64_acc(float acc[8], const float* __restrict__ sW,
                                         int wstride, int cbase,
                                         const float* __restrict__ sA, int lane) {
#pragma unroll 4
    for (int q = 0; q < 16; q++) {
        float a0 = sA[(4 * q + 0) * 32 + lane];
        float a1 = sA[(4 * q + 1) * 32 + lane];
        float a2 = sA[(4 * q + 2) * 32 + lane];
        float a3 = sA[(4 * q + 3) * 32 + lane];
#pragma unroll
        for (int i = 0; i < 8; i++) {
            float4 w = *reinterpret_cast<const float4*>(&sW[(cbase + i) * wstride + 4 * q]);
            acc[i] = fmaf(w.x, a0, acc[i]);
            acc[i] = fmaf(w.y, a1, acc[i]);
            acc[i] = fmaf(w.z, a2, acc[i]);
            acc[i] = fmaf(w.w, a3, acc[i]);
        }
    }
}

// ---------------------------------------------------------------------------
// Kernel A: per-point linear projections — unchanged
// ---------------------------------------------------------------------------
struct SmemA {
    float Wpf[64 * 64];
    float Wqf[64 * 64];
    float Wf1[64 * 64];
    float W1x[64 * 8];
    float Wex[64 * 8];
    float W2x[64 * 8];
    float F1t[64 * 32];
    float F2t[64 * 32];
    float X1[3 * 32];
    float X2[3 * 32];
};

__global__ void kernelA(const float* __restrict__ xyz1, const float* __restrict__ feat1,
                        const float* __restrict__ xyz2, const float* __restrict__ feat2,
                        const float* __restrict__ w10, const float* __restrict__ b10,
                        const float* __restrict__ wx1, const float* __restrict__ bx1,
                        const float* __restrict__ wx2, const float* __restrict__ bx2,
                        const float* __restrict__ w30, const float* __restrict__ b30) {
    extern __shared__ float smem_raw[];
    SmemA& s = *reinterpret_cast<SmemA*>(smem_raw);
    int tid = threadIdx.x;
    int t = blockIdx.x;
    int b = t >> 8;
    int s0 = (t & 255) * 32;

    for (int idx = tid; idx < 4096; idx += 256) {
        int c = idx >> 6, j = idx & 63;
        s.Wpf[idx] = w10[c * 138 + 10 + j];
        s.Wqf[idx] = w10[c * 138 + 74 + j];
        s.Wf1[idx] = w30[c * 192 + 64 + j];
    }
    for (int idx = tid; idx < 384; idx += 256) {
        int c = idx / 6, j = idx % 6;
        s.W1x[c * 8 + j] = w10[c * 138 + j];
        s.Wex[c * 8 + j] = wx1[c * 10 + j];
        s.W2x[c * 8 + j] = wx2[c * 10 + j];
    }
    for (int idx = tid; idx < 2048; idx += 256) {
        int c = idx >> 5, k = idx & 31;
        s.F1t[idx] = feat1[b * CC * SS + c * SS + s0 + k];
        s.F2t[idx] = feat2[b * CC * SS + c * SS + s0 + k];
    }
    for (int idx = tid; idx < 96; idx += 256) {
        int i = idx >> 5, k = idx & 31;
        s.X1[idx] = xyz1[b * 3 * SS + i * SS + s0 + k];
        s.X2[idx] = xyz2[b * 3 * SS + i * SS + s0 + k];
    }
    __syncthreads();

    int lane = tid & 31;
    int cb = (tid >> 5) * 8;
    float x10 = s.X1[lane], x11 = s.X1[32 + lane], x12 = s.X1[64 + lane];
    float x20 = s.X2[lane], x21 = s.X2[32 + lane], x22 = s.X2[64 + lane];

    float accPf[8], accQf[8], accF1[8];
#pragma unroll
    for (int i = 0; i < 8; i++) {
        accPf[i] = __ldg(&b10[cb + i]);
        accQf[i] = 0.f;
        accF1[i] = __ldg(&b30[cb + i]);
    }
    mm64_acc(accPf, s.Wpf, 64, cb, s.F1t, lane);
    mm64_acc(accF1, s.Wf1, 64, cb, s.F1t, lane);
    mm64_acc(accQf, s.Wqf, 64, cb, s.F2t, lane);

#pragma unroll
    for (int i = 0; i < 8; i++) {
        int c = cb + i;
        long base = (long)b * CC * SS + (long)c * SS + s0 + lane;
        float pf = accPf[i] + s.W1x[c * 8 + 0] * x10 + s.W1x[c * 8 + 1] * x11 + s.W1x[c * 8 + 2] * x12;
        float qf = accQf[i] + s.W1x[c * 8 + 3] * x20 + s.W1x[c * 8 + 4] * x21 + s.W1x[c * 8 + 5] * x22;
        g_Pf[base] = pf;
        g_Qf[base] = qf;
        g_F1[base] = accF1[i];
        g_Pe[base] = __ldg(&bx1[c]) + s.Wex[c * 8 + 0] * x10 + s.Wex[c * 8 + 1] * x11 + s.Wex[c * 8 + 2] * x12;
        g_Qe[base] = s.Wex[c * 8 + 3] * x20 + s.Wex[c * 8 + 4] * x21 + s.Wex[c * 8 + 5] * x22;
        g_Ef[base] = __ldg(&bx2[c]) + s.W2x[c * 8 + 0] * x10 + s.W2x[c * 8 + 1] * x11 + s.W2x[c * 8 + 2] * x12;
        g_Eg[base] = s.W2x[c * 8 + 3] * x10 + s.W2x[c * 8 + 4] * x11 + s.W2x[c * 8 + 5] * x12;
    }
}

// ---------------------------------------------------------------------------
// Kernel B: stage 1 — 2 teams; 4 barriers/pass (H fully read by all team warps
// in step 4, so the pre-step1 barrier is mandatory); __fdividef epilogue
// grid = BB*GG*2; 512 threads
// ---------------------------------------------------------------------------
struct SmemB {
    float W11t[64 * WST];
    float W20t[128 * WST];
    float W21t[64 * WST];
    float W1d[64 * 4];
    float Wed[64 * 4];
    float B11[64], B20[64], B21[64];
    float Pf[64 * 16], Pe[64 * 16];     // this half's 16 s-points, [c][slL]
    float X1h[3 * 16];
    float X2[3 * 32];
    float Ha[2][64 * 32], Hb[2][64 * 32];
    float PEa[2][64 * 32], PEb[2][64 * 32];
    float PNa[2][64 * 32], PNb[2][64 * 32];
};

__global__ void __launch_bounds__(512, 1)
kernelB(const float* __restrict__ xyz1, const float* __restrict__ xyz2,
        const float* __restrict__ w10, const float* __restrict__ wx1,
        const float* __restrict__ w11, const float* __restrict__ b11,
        const float* __restrict__ w20, const float* __restrict__ b20,
        const float* __restrict__ w21, const float* __restrict__ b21) {
    extern __shared__ float smem_raw[];
    SmemB& s = *reinterpret_cast<SmemB*>(smem_raw);
    int tid = threadIdx.x;
    int bid = blockIdx.x;
    int b = bid >> 9;
    int g = (bid >> 1) & 255;
    int half = bid & 1;
    int sb = g * MMG;
    int sbh = sb + half * 16;
    long cbase = (long)b * CC * SS;

    for (int idx = tid; idx < 4096; idx += 512) {
        int c = idx >> 6, k = idx & 63;
        s.W11t[k * WST + c] = w11[idx];
        s.W21t[k * WST + c] = w21[idx];
    }
    for (int idx = tid; idx < 8192; idx += 512) {
        int c = idx >> 7, k = idx & 127;
        s.W20t[k * WST + c] = w20[idx];
    }
    if (tid < 256) {
        int c = tid >> 2, j = tid & 3;
        s.W1d[tid] = w10[c * 138 + 6 + j];
        s.Wed[tid] = wx1[c * 10 + 6 + j];
    }
    if (tid < 64) {
        s.B11[tid] = b11[tid];
        s.B20[tid] = b20[tid];
        s.B21[tid] = b21[tid];
    }
    for (int idx = tid; idx < 1024; idx += 512) {
        int c = idx >> 4, sl = idx & 15;
        s.Pf[c * 16 + sl] = g_Pf[cbase + (long)c * SS + sbh + sl];
        s.Pe[c * 16 + sl] = g_Pe[cbase + (long)c * SS + sbh + sl];
    }
    if (tid >= 448 && tid < 496) {
        int i = tid - 448;
        int d = i >> 4, sl = i & 15;
        s.X1h[d * 16 + sl] = xyz1[b * 3 * SS + d * SS + sbh + sl];
    }
    if (tid >= 320 && tid < 416) {
        int i = tid - 320;
        int d = i >> 5, j = i & 31;
        s.X2[d * 32 + j] = xyz2[b * 3 * SS + d * SS + sb + j];
    }
    __syncthreads();

    int lane = tid & 31;
    int wid = tid >> 5;
    int team = wid >> 3;
    int cb = (wid & 7) * 8;
    long outbase = cbase + sb;

    float qf[8], qe[8];
#pragma unroll
    for (int i = 0; i < 8; i++) {
        long base = cbase + (long)(cb + i) * SS + sb + lane;
        qf[i] = __ldg(&g_Qf[base]);
        qe[i] = __ldg(&g_Qe[base]);
    }

    float nx0 = s.X2[lane], nx1 = s.X2[32 + lane], nx2 = s.X2[64 + lane];

    float* Ha = s.Ha[team];  float* Hb = s.Hb[team];
    float* PEa = s.PEa[team]; float* PEb = s.PEb[team];
    float* PNa = s.PNa[team]; float* PNb = s.PNb[team];

    // step 1 for pass p: dynamic parts (H, PE) for s-pair (4p+2t, 4p+2t+1)
    auto do_step1 = [&](int p) {
        int slL0 = 4 * p + 2 * team;
        int slL1 = slL0 + 1;
        float pa0 = s.X1h[slL0], pa1 = s.X1h[16 + slL0], pa2 = s.X1h[32 + slL0];
        float pb0 = s.X1h[slL1], pb1 = s.X1h[16 + slL1], pb2 = s.X1h[32 + slL1];
        float da0 = nx0 - pa0, da1 = nx1 - pa1, da2 = nx2 - pa2;
        float db0 = nx0 - pb0, db1 = nx1 - pb1, db2 = nx2 - pb2;
        float ea = sqrtf(da0 * da0 + da1 * da1 + da2 * da2 + 1e-20f);
        float eb = sqrtf(db0 * db0 + db1 * db1 + db2 * db2 + 1e-20f);
#pragma unroll
        for (int i = 0; i < 8; i++) {
            int c = cb + i;
            float w0 = s.W1d[c * 4 + 0], w1 = s.W1d[c * 4 + 1], w2 = s.W1d[c * 4 + 2], w3 = s.W1d[c * 4 + 3];
            float ha = s.Pf[c * 16 + slL0] + qf[i] + w0 * da0 + w1 * da1 + w2 * da2 + w3 * ea;
            float hb = s.Pf[c * 16 + slL1] + qf[i] + w0 * db0 + w1 * db1 + w2 * db2 + w3 * eb;
            Ha[c * 32 + lane] = fmaxf(ha, 0.f);
            Hb[c * 32 + lane] = fmaxf(hb, 0.f);
            float v0 = s.Wed[c * 4 + 0], v1 = s.Wed[c * 4 + 1], v2 = s.Wed[c * 4 + 2], v3 = s.Wed[c * 4 + 3];
            float pea = s.Pe[c * 16 + slL0] + qe[i] + v0 * da0 + v1 * da1 + v2 * da2 + v3 * ea;
            float peb = s.Pe[c * 16 + slL1] + qe[i] + v0 * db0 + v1 * db1 + v2 * db2 + v3 * eb;
            PEa[c * 32 + lane] = fmaxf(pea, 0.f);
            PEb[c * 32 + lane] = fmaxf(peb, 0.f);
        }
    };

    do_step1(0);
    TEAM_BAR(team);

    for (int p = 0; p < 4; p++) {
        int slL0 = 4 * p + 2 * team;
        int sl0 = half * 16 + slL0;
        int sl1 = sl0 + 1;

        // --- step 2: pi_new = relu(W1_1 @ H + b1_1) ---
        u64 acc0[4], acc1[4];
#pragma unroll
        for (int i = 0; i < 4; i++) {
            u64 bv = *reinterpret_cast<const u64*>(&s.B11[cb + 2 * i]);
            acc0[i] = bv; acc1[i] = bv;
        }
        mmT2(acc0, acc1, s.W11t, cb, Ha, Hb, lane);
#pragma unroll
        for (int i = 0; i < 4; i++) {
            float2 ra = unpack2(acc0[i]), rb = unpack2(acc1[i]);
            PNa[(cb + 2 * i) * 32 + lane] = fmaxf(ra.x, 0.f);
            PNa[(cb + 2 * i + 1) * 32 + lane] = fmaxf(ra.y, 0.f);
            PNb[(cb + 2 * i) * 32 + lane] = fmaxf(rb.x, 0.f);
            PNb[(cb + 2 * i + 1) * 32 + lane] = fmaxf(rb.y, 0.f);
        }
        TEAM_BAR(team);

        // --- step 3: U = relu(W2_0 @ [PE; PN] + b2_0) -> overwrite H (dead after step 2) ---
#pragma unroll
        for (int i = 0; i < 4; i++) {
            u64 bv = *reinterpret_cast<const u64*>(&s.B20[cb + 2 * i]);
            acc0[i] = bv; acc1[i] = bv;
        }
        mmT2(acc0, acc1, s.W20t, cb, PEa, PEb, lane);
        mmT2(acc0, acc1, s.W20t + 64 * WST, cb, PNa, PNb, lane);
#pragma unroll
        for (int i = 0; i < 4; i++) {
            float2 ra = unpack2(acc0[i]), rb = unpack2(acc1[i]);
            Ha[(cb + 2 * i) * 32 + lane] = fmaxf(ra.x, 0.f);
            Ha[(cb + 2 * i + 1) * 32 + lane] = fmaxf(ra.y, 0.f);
            Hb[(cb + 2 * i) * 32 + lane] = fmaxf(rb.x, 0.f);
            Hb[(cb + 2 * i + 1) * 32 + lane] = fmaxf(rb.y, 0.f);
        }
        TEAM_BAR(team);

        // --- step 4: logits = relu(W2_1 @ U + b2_1); softmax; aggregate ---
#pragma unroll
        for (int i = 0; i < 4; i++) {
            u64 bv = *reinterpret_cast<const u64*>(&s.B21[cb + 2 * i]);
            acc0[i] = bv; acc1[i] = bv;
        }
        mmT2(acc0, acc1, s.W21t, cb, Ha, Hb, lane);
#pragma unroll
        for (int i = 0; i < 4; i++) {
            float2 la = unpack2(acc0[i]), lb = unpack2(acc1[i]);
            int c0 = cb + 2 * i, c1 = c0 + 1;
            float pn00 = PNa[c0 * 32 + lane];
            float pn01 = PNa[c1 * 32 + lane];
            float pn10 = PNb[c0 * 32 + lane];
            float pn11 = PNb[c1 * 32 + lane];
            float e00 = __expf(fmaxf(la.x, 0.f));
            float e01 = __expf(fmaxf(la.y, 0.f));
            float e10 = __expf(fmaxf(lb.x, 0.f));
            float e11 = __expf(fmaxf(lb.y, 0.f));
            float2 r00 = warp_rsum2(e00, e00 * pn00);
            float2 r01 = warp_rsum2(e01, e01 * pn01);
            float2 r10 = warp_rsum2(e10, e10 * pn10);
            float2 r11 = warp_rsum2(e11, e11 * pn11);
            if (lane == 0) {
                g_agg[outbase + (long)c0 * SS + sl0] = __fdividef(r00.y, r00.x);
                g_agg[outbase + (long)c1 * SS + sl0] = __fdividef(r01.y, r01.x);
                g_agg[outbase + (long)c0 * SS + sl1] = __fdividef(r10.y, r10.x);
                g_agg[outbase + (long)c1 * SS + sl1] = __fdividef(r11.y, r11.x);
            }
        }
        TEAM_BAR(team);

        if (p < 3) {
            do_step1(p + 1);
            TEAM_BAR(team);
        }
    }
}

// ---------------------------------------------------------------------------
// Kernel C: stage 2 — 2 teams; hoisted G; step1(p+1) overlapped with step3(p)
// grid = BB*GG*2; 512 threads; 2 barriers per pass
// ---------------------------------------------------------------------------
struct SmemC {
    float W30at[64 * WST];
    float W30bt[64 * WST];
    float W31t[64 * WST];
    float W2d[64 * 4];
    float B31[64];
    float Eg[64 * 32], PAG[64 * 32];
    float Ef_h[64 * 16], F1_h[64 * 16];
    float X1[3 * 32];
    float G[64 * 32];
    float Ta[2][64 * 32], Tb[2][64 * 32];
    float Pa[2][64 * 32], Pb[2][64 * 32];
};

__global__ void __launch_bounds__(512, 1)
kernelC(const float* __restrict__ xyz1, const float* __restrict__ wx2,
        const float* __restrict__ w30, const float* __restrict__ w31,
        const float* __restrict__ b31, float* __restrict__ out) {
    extern __shared__ float smem_raw[];
    SmemC& s = *reinterpret_cast<SmemC*>(smem_raw);
    int tid = threadIdx.x;
    int bid = blockIdx.x;
    int b = bid >> 9;
    int g = (bid >> 1) & 255;
    int half = bid & 1;
    int sb = g * MMG;
    int sbh = sb + half * 16;
    long cbase = (long)b * CC * SS;

    for (int idx = tid; idx < 4096; idx += 512) {
        int c = idx >> 6, k = idx & 63;
        s.W30at[k * WST + c] = w30[c * 192 + k];
        s.W30bt[k * WST + c] = w30[c * 192 + 128 + k];
        s.W31t[k * WST + c] = w31[c * 64 + k];
    }
    if (tid < 256) {
        int c = tid >> 2, j = tid & 3;
        s.W2d[tid] = wx2[c * 10 + 6 + j];
    }
    if (tid < 64) s.B31[tid] = b31[tid];
    for (int idx = tid; idx < 2048; idx += 512) {
        int c = idx >> 5, k = idx & 31;
        long base = cbase + (long)c * SS + sb + k;
        s.Eg[idx] = g_Eg[base];
        s.PAG[idx] = g_agg[base];
    }
    for (int idx = tid; idx < 1024; idx += 512) {
        int c = idx >> 4, sl = idx & 15;
        s.Ef_h[c * 16 + sl] = g_Ef[cbase + (long)c * SS + sbh + sl];
        s.F1_h[c * 16 + sl] = g_F1[cbase + (long)c * SS + sbh + sl];
    }
    if (tid >= 384 && tid < 480) {
        int i = tid - 384;
        int d = i >> 5, k = i & 31;
        s.X1[d * 32 + k] = xyz1[b * 3 * SS + d * SS + sb + k];
    }
    __syncthreads();

    int lane = tid & 31;
    int wid = tid >> 5;
    int team = wid >> 3;
    int cb = (wid & 7) * 8;
    long outbase = cbase + sb;

    // --- G = W30b @ pi_agg (s-independent): 16 warps x 4 channels ---
    {
        int c4 = wid * 4;
        u64 gacc[2] = {0ull, 0ull};
#pragma unroll 8
        for (int k = 0; k < 64; k++) {
            ulonglong2 w = *reinterpret_cast<const ulonglong2*>(s.W30bt + k * WST + c4);
            u64 a = splat2(s.PAG[k * 32 + lane]);
            ffma2(gacc[0], w.x, a);
            ffma2(gacc[1], w.y, a);
        }
        float2 v0 = unpack2(gacc[0]), v1 = unpack2(gacc[1]);
        s.G[(c4 + 0) * 32 + lane] = v0.x;
        s.G[(c4 + 1) * 32 + lane] = v0.y;
        s.G[(c4 + 2) * 32 + lane] = v1.x;
        s.G[(c4 + 3) * 32 + lane] = v1.y;
    }
    __syncthreads();

    float nx0 = s.X1[lane], nx1 = s.X1[32 + lane], nx2 = s.X1[64 + lane];

    float* Pa = s.Pa[team]; float* Pb = s.Pb[team];
    float* Ta = s.Ta[team]; float* Tb = s.Tb[team];

    auto do_step1 = [&](int p) {
        int slL0 = 4 * p + 2 * team;
        int slL1 = slL0 + 1;
        int sl0 = half * 16 + slL0;
        int sl1 = sl0 + 1;
        float pa0 = s.X1[sl0], pa1 = s.X1[32 + sl0], pa2 = s.X1[64 + sl0];
        float pb0 = s.X1[sl1], pb1 = s.X1[32 + sl1], pb2 = s.X1[64 + sl1];
        float da0 = nx0 - pa0, da1 = nx1 - pa1, da2 = nx2 - pa2;
        float db0 = nx0 - pb0, db1 = nx1 - pb1, db2 = nx2 - pb2;
        float ea = sqrtf(da0 * da0 + da1 * da1 + da2 * da2 + 1e-20f);
        float eb = sqrtf(db0 * db0 + db1 * db1 + db2 * db2 + 1e-20f);
#pragma unroll
        for (int i = 0; i < 8; i++) {
            int c = cb + i;
            float w0 = s.W2d[c * 4 + 0], w1 = s.W2d[c * 4 + 1], w2 = s.W2d[c * 4 + 2], w3 = s.W2d[c * 4 + 3];
            float base_c = s.Eg[c * 32 + lane];
            float va = s.Ef_h[c * 16 + slL0] + base_c + w0 * da0 + w1 * da1 + w2 * da2 + w3 * ea;
            float vb = s.Ef_h[c * 16 + slL1] + base_c + w0 * db0 + w1 * db1 + w2 * db2 + w3 * eb;
            Pa[c * 32 + lane] = fmaxf(va, 0.f);
            Pb[c * 32 + lane] = fmaxf(vb, 0.f);
        }
    };

    do_step1(0);
    TEAM_BAR(team);

    for (int p = 0; p < 4; p++) {
        int slL0 = 4 * p + 2 * team;
        int slL1 = slL0 + 1;
        int sl0 = half * 16 + slL0;
        int sl1 = sl0 + 1;

        // --- step 2: T = relu(G + F1[.,sl] + W3_0a @ pc_enc) ---
        u64 acc0[4], acc1[4];
#pragma unroll
        for (int i = 0; i < 4; i++) {
            int c0 = cb + 2 * i, c1 = c0 + 1;
            float g0 = s.G[c0 * 32 + lane], g1 = s.G[c1 * 32 + lane];
            acc0[i] = pack2(g0 + s.F1_h[c0 * 16 + slL0], g1 + s.F1_h[c1 * 16 + slL0]);
            acc1[i] = pack2(g0 + s.F1_h[c0 * 16 + slL1], g1 + s.F1_h[c1 * 16 + slL1]);
        }
        mmT2(acc0, acc1, s.W30at, cb, Pa, Pb, lane);
#pragma unroll
        for (int i = 0; i < 4; i++) {
            float2 ra = unpack2(acc0[i]), rb = unpack2(acc1[i]);
            Ta[(cb + 2 * i) * 32 + lane] = fmaxf(ra.x, 0.f);
            Ta[(cb + 2 * i + 1) * 32 + lane] = fmaxf(ra.y, 0.f);
            Tb[(cb + 2 * i) * 32 + lane] = fmaxf(rb.x, 0.f);
            Tb[(cb + 2 * i + 1) * 32 + lane] = fmaxf(rb.y, 0.f);
        }
        TEAM_BAR(team);

        // --- merged phase: step 3 (logits + masked softmax + aggregate)
        //     and step 1(p+1) (writes Pa/Pb, dead after step 2) ---
#pragma unroll
        for (int i = 0; i < 4; i++) {
            u64 bv = *reinterpret_cast<const u64*>(&s.B31[cb + 2 * i]);
            acc0[i] = bv; acc1[i] = bv;
        }
        mmT2(acc0, acc1, s.W31t, cb, Ta, Tb, lane);

        if (p < 3) do_step1(p + 1);   // Pa/Pb are dead (step 2 done team-wide)

#pragma unroll
        for (int i = 0; i < 4; i++) {
            float2 la = unpack2(acc0[i]), lb = unpack2(acc1[i]);
            int c0 = cb + 2 * i, c1 = c0 + 1;
            float pg0 = s.PAG[c0 * 32 + lane];
            float pg1 = s.PAG[c1 * 32 + lane];
            float e00 = (lane == sl0) ? 0.f : __expf(fmaxf(la.x, 0.f));
            float e01 = (lane == sl0) ? 0.f : __expf(fmaxf(la.y, 0.f));
            float e10 = (lane == sl1) ? 0.f : __expf(fmaxf(lb.x, 0.f));
            float e11 = (lane == sl1) ? 0.f : __expf(fmaxf(lb.y, 0.f));
            float2 r00 = warp_rsum2(e00, e00 * pg0);
            float2 r01 = warp_rsum2(e01, e01 * pg1);
            float2 r10 = warp_rsum2(e10, e10 * pg0);
            float2 r11 = warp_rsum2(e11, e11 * pg1);
            if (lane == 0) {
                out[outbase + (long)c0 * SS + sl0] = __fdividef(r00.y, r00.x);
                out[outbase + (long)c1 * SS + sl0] = __fdividef(r01.y, r01.x);
                out[outbase + (long)c0 * SS + sl1] = __fdividef(r10.y, r10.x);
                out[outbase + (long)c1 * SS + sl1] = __fdividef(r11.y, r11.x);
            }
        }
        TEAM_BAR(team);
    }
}

// ---------------------------------------------------------------------------
extern "C" void kernel_launch(void* const* d_in, const int* in_sizes, int n_in,
                              void* d_out, int out_size) {
    const float* xyz1 = (const float*)d_in[0];
    const float* feat1 = (const float*)d_in[1];
    const float* xyz2 = (const float*)d_in[2];
    const float* feat2 = (const float*)d_in[3];
    const float* w10 = (const float*)d_in[4];
    const float* b10 = (const float*)d_in[5];
    const float* w11 = (const float*)d_in[6];
    const float* b11 = (const float*)d_in[7];
    const float* wx1 = (const float*)d_in[8];
    const float* bx1 = (const float*)d_in[9];
    const float* wx2 = (const float*)d_in[10];
    const float* bx2 = (const float*)d_in[11];
    const float* w20 = (const float*)d_in[12];
    const float* b20 = (const float*)d_in[13];
    const float* w21 = (const float*)d_in[14];
    const float* b21 = (const float*)d_in[15];
    const float* w30 = (const float*)d_in[16];
    const float* b30 = (const float*)d_in[17];
    const float* w31 = (const float*)d_in[18];
    const float* b31 = (const float*)d_in[19];
    float* out = (float*)d_out;

    cudaFuncSetAttribute(kernelA, cudaFuncAttributeMaxDynamicSharedMemorySize, (int)sizeof(SmemA));
    cudaFuncSetAttribute(kernelB, cudaFuncAttributeMaxDynamicSharedMemorySize, (int)sizeof(SmemB));
    cudaFuncSetAttribute(kernelC, cudaFuncAttributeMaxDynamicSharedMemorySize, (int)sizeof(SmemC));

    kernelA<<<(BB * SS) / 32, 256, sizeof(SmemA)>>>(xyz1, feat1, xyz2, feat2,
                                                    w10, b10, wx1, bx1, wx2, bx2, w30, b30);
    kernelB<<<BB * GG * 2, 512, sizeof(SmemB)>>>(xyz1, xyz2, w10, wx1,
                                                 w11, b11, w20, b20, w21, b21);
    kernelC<<<BB * GG * 2, 512, sizeof(SmemC)>>>(xyz1, wx2, w30, w31, b31, out);
}

// round 13
// speedup vs baseline: 1.1082x; 1.0028x over previous
#include <cuda_runtime.h>
#include <math.h>

// Problem constants
#define BB 2
#define SS 8192
#define CC 64
#define MMG 32
#define GG (SS / MMG)          // 256 groups per batch
#define BCS (BB * CC * SS)
#define WST 64                 // weight row stride ([k][c] layout; broadcast loads)

// Scratch (device globals — allocation-free)
__device__ float g_Pf[BCS];
__device__ float g_Qf[BCS];
__device__ float g_Pe[BCS];
__device__ float g_Qe[BCS];
__device__ float g_Ef[BCS];
__device__ float g_Eg[BCS];
__device__ float g_F1[BCS];
__device__ float g_agg[BCS];

typedef unsigned long long u64;

// per-team named barrier: 256 threads of team t sync on barrier id t+1
#define TEAM_BAR(t) asm volatile("bar.sync %0, 256;" :: "r"((t) + 1) : "memory")

// ---------------------------------------------------------------------------
// packed fp32 helpers (Blackwell f32x2) + warp reduction
// ---------------------------------------------------------------------------
__device__ __forceinline__ void ffma2(u64& d, u64 a, u64 b) {
    asm("fma.rn.f32x2 %0, %1, %2, %0;" : "+l"(d) : "l"(a), "l"(b));
}
__device__ __forceinline__ u64 splat2(float a) {
    u64 r; asm("mov.b64 %0, {%1, %1};" : "=l"(r) : "f"(a)); return r;
}
__device__ __forceinline__ u64 pack2(float x, float y) {
    u64 r; asm("mov.b64 %0, {%1, %2};" : "=l"(r) : "f"(x), "f"(y)); return r;
}
__device__ __forceinline__ float2 unpack2(u64 v) {
    float2 r; asm("mov.b64 {%0, %1}, %2;" : "=f"(r.x), "=f"(r.y) : "l"(v)); return r;
}
// two interleaved butterfly sums (sm_100 has no redux.f32)
__device__ __forceinline__ float2 warp_rsum2(float a, float b) {
#pragma unroll
    for (int o = 16; o > 0; o >>= 1) {
        a += __shfl_xor_sync(0xffffffffu, a, o);
        b += __shfl_xor_sync(0xffffffffu, b, o);
    }
    return make_float2(a, b);
}

// Packed matmul over K=64: acc{0,1}[i] += Wt[k][cb+2i..] * A{0,1}[k][lane]
__device__ __forceinline__ void mmT2(u64 acc0[4], u64 acc1[4],
                                     const float* __restrict__ sWt, int cb,
                                     const float* __restrict__ sA0,
                                     const float* __restrict__ sA1, int lane) {
#pragma unroll 8
    for (int k = 0; k < 64; k++) {
        ulonglong2 wlo = *reinterpret_cast<const ulonglong2*>(sWt + k * WST + cb);
        ulonglong2 whi = *reinterpret_cast<const ulonglong2*>(sWt + k * WST + cb + 4);
        u64 a0 = splat2(sA0[k * 32 + lane]);
        u64 a1 = splat2(sA1[k * 32 + lane]);
        ffma2(acc0[0], wlo.x, a0); ffma2(acc0[1], wlo.y, a0);
        ffma2(acc0[2], whi.x, a0); ffma2(acc0[3], whi.y, a0);
        ffma2(acc1[0], wlo.x, a1); ffma2(acc1[1], wlo.y, a1);
        ffma2(acc1[2], whi.x, a1); ffma2(acc1[3], whi.y, a1);
    }
}

// scalar helper used by kernel A
__device__ __forceinline__ void mm64_acc(float acc[8], const float* __restrict__ sW,
                                         int wstride, int cbase,
                                         const float* __restrict__ sA, int lane) {
#pragma unroll 4
    for (int q = 0; q < 16; q++) {
        float a0 = sA[(4 * q + 0) * 32 + lane];
        float a1 = sA[(4 * q + 1) * 32 + lane];
        float a2 = sA[(4 * q + 2) * 32 + lane];
        float a3 = sA[(4 * q + 3) * 32 + lane];
#pragma unroll
        for (int i = 0; i < 8; i++) {
            float4 w = *reinterpret_cast<const float4*>(&sW[(cbase + i) * wstride + 4 * q]);
            acc[i] = fmaf(w.x, a0, acc[i]);
            acc[i] = fmaf(w.y, a1, acc[i]);
            acc[i] = fmaf(w.z, a2, acc[i]);
            acc[i] = fmaf(w.w, a3, acc[i]);
        }
    }
}

// ---------------------------------------------------------------------------
// Kernel A: per-point linear projections — unchanged
// ---------------------------------------------------------------------------
struct SmemA {
    float Wpf[64 * 64];
    float Wqf[64 * 64];
    float Wf1[64 * 64];
    float W1x[64 * 8];
    float Wex[64 * 8];
    float W2x[64 * 8];
    float F1t[64 * 32];
    float F2t[64 * 32];
    float X1[3 * 32];
    float X2[3 * 32];
};

__global__ void kernelA(const float* __restrict__ xyz1, const float* __restrict__ feat1,
                        const float* __restrict__ xyz2, const float* __restrict__ feat2,
                        const float* __restrict__ w10, const float* __restrict__ b10,
                        const float* __restrict__ wx1, const float* __restrict__ bx1,
                        const float* __restrict__ wx2, const float* __restrict__ bx2,
                        const float* __restrict__ w30, const float* __restrict__ b30) {
    extern __shared__ float smem_raw[];
    SmemA& s = *reinterpret_cast<SmemA*>(smem_raw);
    int tid = threadIdx.x;
    int t = blockIdx.x;
    int b = t >> 8;
    int s0 = (t & 255) * 32;

    for (int idx = tid; idx < 4096; idx += 256) {
        int c = idx >> 6, j = idx & 63;
        s.Wpf[idx] = w10[c * 138 + 10 + j];
        s.Wqf[idx] = w10[c * 138 + 74 + j];
        s.Wf1[idx] = w30[c * 192 + 64 + j];
    }
    for (int idx = tid; idx < 384; idx += 256) {
        int c = idx / 6, j = idx % 6;
        s.W1x[c * 8 + j] = w10[c * 138 + j];
        s.Wex[c * 8 + j] = wx1[c * 10 + j];
        s.W2x[c * 8 + j] = wx2[c * 10 + j];
    }
    for (int idx = tid; idx < 2048; idx += 256) {
        int c = idx >> 5, k = idx & 31;
        s.F1t[idx] = feat1[b * CC * SS + c * SS + s0 + k];
        s.F2t[idx] = feat2[b * CC * SS + c * SS + s0 + k];
    }
    for (int idx = tid; idx < 96; idx += 256) {
        int i = idx >> 5, k = idx & 31;
        s.X1[idx] = xyz1[b * 3 * SS + i * SS + s0 + k];
        s.X2[idx] = xyz2[b * 3 * SS + i * SS + s0 + k];
    }
    __syncthreads();

    int lane = tid & 31;
    int cb = (tid >> 5) * 8;
    float x10 = s.X1[lane], x11 = s.X1[32 + lane], x12 = s.X1[64 + lane];
    float x20 = s.X2[lane], x21 = s.X2[32 + lane], x22 = s.X2[64 + lane];

    float accPf[8], accQf[8], accF1[8];
#pragma unroll
    for (int i = 0; i < 8; i++) {
        accPf[i] = __ldg(&b10[cb + i]);
        accQf[i] = 0.f;
        accF1[i] = __ldg(&b30[cb + i]);
    }
    mm64_acc(accPf, s.Wpf, 64, cb, s.F1t, lane);
    mm64_acc(accF1, s.Wf1, 64, cb, s.F1t, lane);
    mm64_acc(accQf, s.Wqf, 64, cb, s.F2t, lane);

#pragma unroll
    for (int i = 0; i < 8; i++) {
        int c = cb + i;
        long base = (long)b * CC * SS + (long)c * SS + s0 + lane;
        float pf = accPf[i] + s.W1x[c * 8 + 0] * x10 + s.W1x[c * 8 + 1] * x11 + s.W1x[c * 8 + 2] * x12;
        float qf = accQf[i] + s.W1x[c * 8 + 3] * x20 + s.W1x[c * 8 + 4] * x21 + s.W1x[c * 8 + 5] * x22;
        g_Pf[base] = pf;
        g_Qf[base] = qf;
        g_F1[base] = accF1[i];
        g_Pe[base] = __ldg(&bx1[c]) + s.Wex[c * 8 + 0] * x10 + s.Wex[c * 8 + 1] * x11 + s.Wex[c * 8 + 2] * x12;
        g_Qe[base] = s.Wex[c * 8 + 3] * x20 + s.Wex[c * 8 + 4] * x21 + s.Wex[c * 8 + 5] * x22;
        g_Ef[base] = __ldg(&bx2[c]) + s.W2x[c * 8 + 0] * x10 + s.W2x[c * 8 + 1] * x11 + s.W2x[c * 8 + 2] * x12;
        g_Eg[base] = s.W2x[c * 8 + 3] * x10 + s.W2x[c * 8 + 4] * x11 + s.W2x[c * 8 + 5] * x12;
    }
}

// ---------------------------------------------------------------------------
// Kernel B: stage 1 — 2 teams; dedicated U buffers -> merged step4+step1(p+1)
// grid = BB*GG*2; 512 threads; 3 barriers per pass
// ---------------------------------------------------------------------------
struct SmemB {
    float W11t[64 * WST];
    float W20t[128 * WST];
    float W21t[64 * WST];
    float W1d[64 * 4];
    float Wed[64 * 4];
    float B11[64], B20[64], B21[64];
    float Pf[64 * 16], Pe[64 * 16];     // this half's 16 s-points, [c][slL]
    float X1h[3 * 16];
    float X2[3 * 32];
    float Ha[2][64 * 32], Hb[2][64 * 32];
    float PEa[2][64 * 32], PEb[2][64 * 32];
    float PNa[2][64 * 32], PNb[2][64 * 32];
    float Ua[2][64 * 32], Ub[2][64 * 32];   // dedicated U buffers (legalize merge)
};

__global__ void __launch_bounds__(512, 1)
kernelB(const float* __restrict__ xyz1, const float* __restrict__ xyz2,
        const float* __restrict__ w10, const float* __restrict__ wx1,
        const float* __restrict__ w11, const float* __restrict__ b11,
        const float* __restrict__ w20, const float* __restrict__ b20,
        const float* __restrict__ w21, const float* __restrict__ b21) {
    extern __shared__ float smem_raw[];
    SmemB& s = *reinterpret_cast<SmemB*>(smem_raw);
    int tid = threadIdx.x;
    int bid = blockIdx.x;
    int b = bid >> 9;
    int g = (bid >> 1) & 255;
    int half = bid & 1;
    int sb = g * MMG;
    int sbh = sb + half * 16;
    long cbase = (long)b * CC * SS;

    for (int idx = tid; idx < 4096; idx += 512) {
        int c = idx >> 6, k = idx & 63;
        s.W11t[k * WST + c] = w11[idx];
        s.W21t[k * WST + c] = w21[idx];
    }
    for (int idx = tid; idx < 8192; idx += 512) {
        int c = idx >> 7, k = idx & 127;
        s.W20t[k * WST + c] = w20[idx];
    }
    if (tid < 256) {
        int c = tid >> 2, j = tid & 3;
        s.W1d[tid] = w10[c * 138 + 6 + j];
        s.Wed[tid] = wx1[c * 10 + 6 + j];
    }
    if (tid < 64) {
        s.B11[tid] = b11[tid];
        s.B20[tid] = b20[tid];
        s.B21[tid] = b21[tid];
    }
    for (int idx = tid; idx < 1024; idx += 512) {
        int c = idx >> 4, sl = idx & 15;
        s.Pf[c * 16 + sl] = g_Pf[cbase + (long)c * SS + sbh + sl];
        s.Pe[c * 16 + sl] = g_Pe[cbase + (long)c * SS + sbh + sl];
    }
    if (tid >= 448 && tid < 496) {
        int i = tid - 448;
        int d = i >> 4, sl = i & 15;
        s.X1h[d * 16 + sl] = xyz1[b * 3 * SS + d * SS + sbh + sl];
    }
    if (tid >= 320 && tid < 416) {
        int i = tid - 320;
        int d = i >> 5, j = i & 31;
        s.X2[d * 32 + j] = xyz2[b * 3 * SS + d * SS + sb + j];
    }
    __syncthreads();

    int lane = tid & 31;
    int wid = tid >> 5;
    int team = wid >> 3;
    int cb = (wid & 7) * 8;
    long outbase = cbase + sb;

    float qf[8], qe[8];
#pragma unroll
    for (int i = 0; i < 8; i++) {
        long base = cbase + (long)(cb + i) * SS + sb + lane;
        qf[i] = __ldg(&g_Qf[base]);
        qe[i] = __ldg(&g_Qe[base]);
    }

    float nx0 = s.X2[lane], nx1 = s.X2[32 + lane], nx2 = s.X2[64 + lane];

    float* Ha = s.Ha[team];  float* Hb = s.Hb[team];
    float* PEa = s.PEa[team]; float* PEb = s.PEb[team];
    float* PNa = s.PNa[team]; float* PNb = s.PNb[team];
    float* Ua = s.Ua[team];  float* Ub = s.Ub[team];

    // step 1 for pass p: dynamic parts (H, PE) for s-pair (4p+2t, 4p+2t+1)
    auto do_step1 = [&](int p) {
        int slL0 = 4 * p + 2 * team;
        int slL1 = slL0 + 1;
        float pa0 = s.X1h[slL0], pa1 = s.X1h[16 + slL0], pa2 = s.X1h[32 + slL0];
        float pb0 = s.X1h[slL1], pb1 = s.X1h[16 + slL1], pb2 = s.X1h[32 + slL1];
        float da0 = nx0 - pa0, da1 = nx1 - pa1, da2 = nx2 - pa2;
        float db0 = nx0 - pb0, db1 = nx1 - pb1, db2 = nx2 - pb2;
        float ea = sqrtf(da0 * da0 + da1 * da1 + da2 * da2 + 1e-20f);
        float eb = sqrtf(db0 * db0 + db1 * db1 + db2 * db2 + 1e-20f);
#pragma unroll
        for (int i = 0; i < 8; i++) {
            int c = cb + i;
            float w0 = s.W1d[c * 4 + 0], w1 = s.W1d[c * 4 + 1], w2 = s.W1d[c * 4 + 2], w3 = s.W1d[c * 4 + 3];
            float ha = s.Pf[c * 16 + slL0] + qf[i] + w0 * da0 + w1 * da1 + w2 * da2 + w3 * ea;
            float hb = s.Pf[c * 16 + slL1] + qf[i] + w0 * db0 + w1 * db1 + w2 * db2 + w3 * eb;
            Ha[c * 32 + lane] = fmaxf(ha, 0.f);
            Hb[c * 32 + lane] = fmaxf(hb, 0.f);
            float v0 = s.Wed[c * 4 + 0], v1 = s.Wed[c * 4 + 1], v2 = s.Wed[c * 4 + 2], v3 = s.Wed[c * 4 + 3];
            float pea = s.Pe[c * 16 + slL0] + qe[i] + v0 * da0 + v1 * da1 + v2 * da2 + v3 * ea;
            float peb = s.Pe[c * 16 + slL1] + qe[i] + v0 * db0 + v1 * db1 + v2 * db2 + v3 * eb;
            PEa[c * 32 + lane] = fmaxf(pea, 0.f);
            PEb[c * 32 + lane] = fmaxf(peb, 0.f);
        }
    };

    do_step1(0);
    TEAM_BAR(team);

    for (int p = 0; p < 4; p++) {
        int slL0 = 4 * p + 2 * team;
        int sl0 = half * 16 + slL0;
        int sl1 = sl0 + 1;

        // --- step 2: pi_new = relu(W1_1 @ H + b1_1) ---
        u64 acc0[4], acc1[4];
#pragma unroll
        for (int i = 0; i < 4; i++) {
            u64 bv = *reinterpret_cast<const u64*>(&s.B11[cb + 2 * i]);
            acc0[i] = bv; acc1[i] = bv;
        }
        mmT2(acc0, acc1, s.W11t, cb, Ha, Hb, lane);
#pragma unroll
        for (int i = 0; i < 4; i++) {
            float2 ra = unpack2(acc0[i]), rb = unpack2(acc1[i]);
            PNa[(cb + 2 * i) * 32 + lane] = fmaxf(ra.x, 0.f);
            PNa[(cb + 2 * i + 1) * 32 + lane] = fmaxf(ra.y, 0.f);
            PNb[(cb + 2 * i) * 32 + lane] = fmaxf(rb.x, 0.f);
            PNb[(cb + 2 * i + 1) * 32 + lane] = fmaxf(rb.y, 0.f);
        }
        TEAM_BAR(team);

        // --- step 3: U = relu(W2_0 @ [PE; PN] + b2_0) -> dedicated Ua/Ub ---
#pragma unroll
        for (int i = 0; i < 4; i++) {
            u64 bv = *reinterpret_cast<const u64*>(&s.B20[cb + 2 * i]);
            acc0[i] = bv; acc1[i] = bv;
        }
        mmT2(acc0, acc1, s.W20t, cb, PEa, PEb, lane);
        mmT2(acc0, acc1, s.W20t + 64 * WST, cb, PNa, PNb, lane);
#pragma unroll
        for (int i = 0; i < 4; i++) {
            float2 ra = unpack2(acc0[i]), rb = unpack2(acc1[i]);
            Ua[(cb + 2 * i) * 32 + lane] = fmaxf(ra.x, 0.f);
            Ua[(cb + 2 * i + 1) * 32 + lane] = fmaxf(ra.y, 0.f);
            Ub[(cb + 2 * i) * 32 + lane] = fmaxf(rb.x, 0.f);
            Ub[(cb + 2 * i + 1) * 32 + lane] = fmaxf(rb.y, 0.f);
        }
        TEAM_BAR(team);

        // --- merged phase: step 4 (reads U, PN) + step 1(p+1) (writes H', PE') ---
        // H dead since step 2's barrier; PE dead since step 3's barrier.
#pragma unroll
        for (int i = 0; i < 4; i++) {
            u64 bv = *reinterpret_cast<const u64*>(&s.B21[cb + 2 * i]);
            acc0[i] = bv; acc1[i] = bv;
        }
        mmT2(acc0, acc1, s.W21t, cb, Ua, Ub, lane);

        if (p < 3) do_step1(p + 1);

#pragma unroll
        for (int i = 0; i < 4; i++) {
            float2 la = unpack2(acc0[i]), lb = unpack2(acc1[i]);
            int c0 = cb + 2 * i, c1 = c0 + 1;
            float pn00 = PNa[c0 * 32 + lane];
            float pn01 = PNa[c1 * 32 + lane];
            float pn10 = PNb[c0 * 32 + lane];
            float pn11 = PNb[c1 * 32 + lane];
            float e00 = __expf(fmaxf(la.x, 0.f));
            float e01 = __expf(fmaxf(la.y, 0.f));
            float e10 = __expf(fmaxf(lb.x, 0.f));
            float e11 = __expf(fmaxf(lb.y, 0.f));
            float2 r00 = warp_rsum2(e00, e00 * pn00);
            float2 r01 = warp_rsum2(e01, e01 * pn01);
            float2 r10 = warp_rsum2(e10, e10 * pn10);
            float2 r11 = warp_rsum2(e11, e11 * pn11);
            if (lane == 0) {
                g_agg[outbase + (long)c0 * SS + sl0] = __fdividef(r00.y, r00.x);
                g_agg[outbase + (long)c1 * SS + sl0] = __fdividef(r01.y, r01.x);
                g_agg[outbase + (long)c0 * SS + sl1] = __fdividef(r10.y, r10.x);
                g_agg[outbase + (long)c1 * SS + sl1] = __fdividef(r11.y, r11.x);
            }
        }
        TEAM_BAR(team);
    }
}

// ---------------------------------------------------------------------------
// Kernel C: stage 2 — unchanged from R12 (2 barriers/pass, merged step3+step1')
// ---------------------------------------------------------------------------
struct SmemC {
    float W30at[64 * WST];
    float W30bt[64 * WST];
    float W31t[64 * WST];
    float W2d[64 * 4];
    float B31[64];
    float Eg[64 * 32], PAG[64 * 32];
    float Ef_h[64 * 16], F1_h[64 * 16];
    float X1[3 * 32];
    float G[64 * 32];
    float Ta[2][64 * 32], Tb[2][64 * 32];
    float Pa[2][64 * 32], Pb[2][64 * 32];
};

__global__ void __launch_bounds__(512, 1)
kernelC(const float* __restrict__ xyz1, const float* __restrict__ wx2,
        const float* __restrict__ w30, const float* __restrict__ w31,
        const float* __restrict__ b31, float* __restrict__ out) {
    extern __shared__ float smem_raw[];
    SmemC& s = *reinterpret_cast<SmemC*>(smem_raw);
    int tid = threadIdx.x;
    int bid = blockIdx.x;
    int b = bid >> 9;
    int g = (bid >> 1) & 255;
    int half = bid & 1;
    int sb = g * MMG;
    int sbh = sb + half * 16;
    long cbase = (long)b * CC * SS;

    for (int idx = tid; idx < 4096; idx += 512) {
        int c = idx >> 6, k = idx & 63;
        s.W30at[k * WST + c] = w30[c * 192 + k];
        s.W30bt[k * WST + c] = w30[c * 192 + 128 + k];
        s.W31t[k * WST + c] = w31[c * 64 + k];
    }
    if (tid < 256) {
        int c = tid >> 2, j = tid & 3;
        s.W2d[tid] = wx2[c * 10 + 6 + j];
    }
    if (tid < 64) s.B31[tid] = b31[tid];
    for (int idx = tid; idx < 2048; idx += 512) {
        int c = idx >> 5, k = idx & 31;
        long base = cbase + (long)c * SS + sb + k;
        s.Eg[idx] = g_Eg[base];
        s.PAG[idx] = g_agg[base];
    }
    for (int idx = tid; idx < 1024; idx += 512) {
        int c = idx >> 4, sl = idx & 15;
        s.Ef_h[c * 16 + sl] = g_Ef[cbase + (long)c * SS + sbh + sl];
        s.F1_h[c * 16 + sl] = g_F1[cbase + (long)c * SS + sbh + sl];
    }
    if (tid >= 384 && tid < 480) {
        int i = tid - 384;
        int d = i >> 5, k = i & 31;
        s.X1[d * 32 + k] = xyz1[b * 3 * SS + d * SS + sb + k];
    }
    __syncthreads();

    int lane = tid & 31;
    int wid = tid >> 5;
    int team = wid >> 3;
    int cb = (wid & 7) * 8;
    long outbase = cbase + sb;

    // --- G = W30b @ pi_agg (s-independent): 16 warps x 4 channels ---
    {
        int c4 = wid * 4;
        u64 gacc[2] = {0ull, 0ull};
#pragma unroll 8
        for (int k = 0; k < 64; k++) {
            ulonglong2 w = *reinterpret_cast<const ulonglong2*>(s.W30bt + k * WST + c4);
            u64 a = splat2(s.PAG[k * 32 + lane]);
            ffma2(gacc[0], w.x, a);
            ffma2(gacc[1], w.y, a);
        }
        float2 v0 = unpack2(gacc[0]), v1 = unpack2(gacc[1]);
        s.G[(c4 + 0) * 32 + lane] = v0.x;
        s.G[(c4 + 1) * 32 + lane] = v0.y;
        s.G[(c4 + 2) * 32 + lane] = v1.x;
        s.G[(c4 + 3) * 32 + lane] = v1.y;
    }
    __syncthreads();

    float nx0 = s.X1[lane], nx1 = s.X1[32 + lane], nx2 = s.X1[64 + lane];

    float* Pa = s.Pa[team]; float* Pb = s.Pb[team];
    float* Ta = s.Ta[team]; float* Tb = s.Tb[team];

    auto do_step1 = [&](int p) {
        int slL0 = 4 * p + 2 * team;
        int slL1 = slL0 + 1;
        int sl0 = half * 16 + slL0;
        int sl1 = sl0 + 1;
        float pa0 = s.X1[sl0], pa1 = s.X1[32 + sl0], pa2 = s.X1[64 + sl0];
        float pb0 = s.X1[sl1], pb1 = s.X1[32 + sl1], pb2 = s.X1[64 + sl1];
        float da0 = nx0 - pa0, da1 = nx1 - pa1, da2 = nx2 - pa2;
        float db0 = nx0 - pb0, db1 = nx1 - pb1, db2 = nx2 - pb2;
        float ea = sqrtf(da0 * da0 + da1 * da1 + da2 * da2 + 1e-20f);
        float eb = sqrtf(db0 * db0 + db1 * db1 + db2 * db2 + 1e-20f);
#pragma unroll
        for (int i = 0; i < 8; i++) {
            int c = cb + i;
            float w0 = s.W2d[c * 4 + 0], w1 = s.W2d[c * 4 + 1], w2 = s.W2d[c * 4 + 2], w3 = s.W2d[c * 4 + 3];
            float base_c = s.Eg[c * 32 + lane];
            float va = s.Ef_h[c * 16 + slL0] + base_c + w0 * da0 + w1 * da1 + w2 * da2 + w3 * ea;
            float vb = s.Ef_h[c * 16 + slL1] + base_c + w0 * db0 + w1 * db1 + w2 * db2 + w3 * eb;
            Pa[c * 32 + lane] = fmaxf(va, 0.f);
            Pb[c * 32 + lane] = fmaxf(vb, 0.f);
        }
    };

    do_step1(0);
    TEAM_BAR(team);

    for (int p = 0; p < 4; p++) {
        int slL0 = 4 * p + 2 * team;
        int slL1 = slL0 + 1;
        int sl0 = half * 16 + slL0;
        int sl1 = sl0 + 1;

        // --- step 2: T = relu(G + F1[.,sl] + W3_0a @ pc_enc) ---
        u64 acc0[4], acc1[4];
#pragma unroll
        for (int i = 0; i < 4; i++) {
            int c0 = cb + 2 * i, c1 = c0 + 1;
            float g0 = s.G[c0 * 32 + lane], g1 = s.G[c1 * 32 + lane];
            acc0[i] = pack2(g0 + s.F1_h[c0 * 16 + slL0], g1 + s.F1_h[c1 * 16 + slL0]);
            acc1[i] = pack2(g0 + s.F1_h[c0 * 16 + slL1], g1 + s.F1_h[c1 * 16 + slL1]);
        }
        mmT2(acc0, acc1, s.W30at, cb, Pa, Pb, lane);
#pragma unroll
        for (int i = 0; i < 4; i++) {
            float2 ra = unpack2(acc0[i]), rb = unpack2(acc1[i]);
            Ta[(cb + 2 * i) * 32 + lane] = fmaxf(ra.x, 0.f);
            Ta[(cb + 2 * i + 1) * 32 + lane] = fmaxf(ra.y, 0.f);
            Tb[(cb + 2 * i) * 32 + lane] = fmaxf(rb.x, 0.f);
            Tb[(cb + 2 * i + 1) * 32 + lane] = fmaxf(rb.y, 0.f);
        }
        TEAM_BAR(team);

        // --- merged phase: step 3 (logits + masked softmax + aggregate)
        //     and step 1(p+1) (writes Pa/Pb, dead after step 2) ---
#pragma unroll
        for (int i = 0; i < 4; i++) {
            u64 bv = *reinterpret_cast<const u64*>(&s.B31[cb + 2 * i]);
            acc0[i] = bv; acc1[i] = bv;
        }
        mmT2(acc0, acc1, s.W31t, cb, Ta, Tb, lane);

        if (p < 3) do_step1(p + 1);   // Pa/Pb are dead (step 2 done team-wide)

#pragma unroll
        for (int i = 0; i < 4; i++) {
            float2 la = unpack2(acc0[i]), lb = unpack2(acc1[i]);
            int c0 = cb + 2 * i, c1 = c0 + 1;
            float pg0 = s.PAG[c0 * 32 + lane];
            float pg1 = s.PAG[c1 * 32 + lane];
            float e00 = (lane == sl0) ? 0.f : __expf(fmaxf(la.x, 0.f));
            float e01 = (lane == sl0) ? 0.f : __expf(fmaxf(la.y, 0.f));
            float e10 = (lane == sl1) ? 0.f : __expf(fmaxf(lb.x, 0.f));
            float e11 = (lane == sl1) ? 0.f : __expf(fmaxf(lb.y, 0.f));
            float2 r00 = warp_rsum2(e00, e00 * pg0);
            float2 r01 = warp_rsum2(e01, e01 * pg1);
            float2 r10 = warp_rsum2(e10, e10 * pg0);
            float2 r11 = warp_rsum2(e11, e11 * pg1);
            if (lane == 0) {
                out[outbase + (long)c0 * SS + sl0] = __fdividef(r00.y, r00.x);
                out[outbase + (long)c1 * SS + sl0] = __fdividef(r01.y, r01.x);
                out[outbase + (long)c0 * SS + sl1] = __fdividef(r10.y, r10.x);
                out[outbase + (long)c1 * SS + sl1] = __fdividef(r11.y, r11.x);
            }
        }
        TEAM_BAR(team);
    }
}

// ---------------------------------------------------------------------------
extern "C" void kernel_launch(void* const* d_in, const int* in_sizes, int n_in,
                              void* d_out, int out_size) {
    const float* xyz1 = (const float*)d_in[0];
    const float* feat1 = (const float*)d_in[1];
    const float* xyz2 = (const float*)d_in[2];
    const float* feat2 = (const float*)d_in[3];
    const float* w10 = (const float*)d_in[4];
    const float* b10 = (const float*)d_in[5];
    const float* w11 = (const float*)d_in[6];
    const float* b11 = (const float*)d_in[7];
    const float* wx1 = (const float*)d_in[8];
    const float* bx1 = (const float*)d_in[9];
    const float* wx2 = (const float*)d_in[10];
    const float* bx2 = (const float*)d_in[11];
    const float* w20 = (const float*)d_in[12];
    const float* b20 = (const float*)d_in[13];
    const float* w21 = (const float*)d_in[14];
    const float* b21 = (const float*)d_in[15];
    const float* w30 = (const float*)d_in[16];
    const float* b30 = (const float*)d_in[17];
    const float* w31 = (const float*)d_in[18];
    const float* b31 = (const float*)d_in[19];
    float* out = (float*)d_out;

    cudaFuncSetAttribute(kernelA, cudaFuncAttributeMaxDynamicSharedMemorySize, (int)sizeof(SmemA));
    cudaFuncSetAttribute(kernelB, cudaFuncAttributeMaxDynamicSharedMemorySize, (int)sizeof(SmemB));
    cudaFuncSetAttribute(kernelC, cudaFuncAttributeMaxDynamicSharedMemorySize, (int)sizeof(SmemC));

    kernelA<<<(BB * SS) / 32, 256, sizeof(SmemA)>>>(xyz1, feat1, xyz2, feat2,
                                                    w10, b10, wx1, bx1, wx2, bx2, w30, b30);
    kernelB<<<BB * GG * 2, 512, sizeof(SmemB)>>>(xyz1, xyz2, w10, wx1,
                                                 w11, b11, w20, b20, w21, b21);
    kernelC<<<BB * GG * 2, 512, sizeof(SmemC)>>>(xyz1, wx2, w30, w31, b31, out);
}